// round 5
// baseline (speedup 1.0000x reference)
#include <cuda_runtime.h>
#include <cuda_bf16.h>
#include <cstdint>

// Problem constants (fixed by the dataset's setup_inputs)
#define NNODES 100000
#define NEDGES 50000
#define EDGESZ 16
#define NMEMB  (NEDGES * EDGESZ)   // 800000
#define DIM    128

// Scratch (allocation-free rule: __device__ globals)
__device__ float g_w2[NNODES];
__device__ float g_edge_sum[(size_t)NEDGES * DIM];
__device__ int   g_deg[NNODES];
__device__ int   g_cnt[NNODES];
__device__ int   g_off[NNODES];
__device__ int   g_elist[NMEMB];   // node -> list of incident edges
__device__ int   g_ctr;

// ---------------------------------------------------------------------------
// packed f32x2 helpers
// ---------------------------------------------------------------------------
__device__ __forceinline__ void fma2(unsigned long long& d,
                                     unsigned long long a, unsigned long long b)
{
    asm("fma.rn.f32x2 %0, %1, %2, %0;" : "+l"(d) : "l"(a), "l"(b));
}
__device__ __forceinline__ unsigned long long pk2(float lo, float hi)
{
    unsigned long long r;
    asm("mov.b64 %0, {%1, %2};" : "=l"(r) : "f"(lo), "f"(hi));
    return r;
}
__device__ __forceinline__ void unpk2(float& lo, float& hi, unsigned long long v)
{
    asm("mov.b64 {%0, %1}, %2;" : "=f"(lo), "=f"(hi) : "l"(v));
}

// ---------------------------------------------------------------------------
// Kernel W: per-node MLP -> w2[n]; zero deg/cnt/ctr
// ---------------------------------------------------------------------------
__global__ __launch_bounds__(256) void kW(
    const float* __restrict__ iw,
    const float* __restrict__ fc1w, const float* __restrict__ fc1b,
    const float* __restrict__ fc2w, const float* __restrict__ fc2b,
    const float* __restrict__ fc3w, const float* __restrict__ fc3b)
{
    int n = blockIdx.x * 256 + threadIdx.x;
    if (n == 0) g_ctr = 0;
    if (n >= NNODES) return;
    float x0 = iw[n * 2 + 0];
    float x1 = iw[n * 2 + 1];
    float h1[10];
#pragma unroll
    for (int j = 0; j < 10; j++)
        h1[j] = fmaxf(0.f, fmaf(x0, fc1w[j], fmaf(x1, fc1w[10 + j], fc1b[j])));
    float h2[5];
#pragma unroll
    for (int j = 0; j < 5; j++) {
        float s = fc2b[j];
#pragma unroll
        for (int k = 0; k < 10; k++) s = fmaf(h1[k], fc2w[k * 5 + j], s);
        h2[j] = fmaxf(0.f, s);
    }
    float z = fc3b[0];
#pragma unroll
    for (int k = 0; k < 5; k++) z = fmaf(h2[k], fc3w[k], z);
    g_w2[n] = 1.f / (1.f + expf(-z));
    g_deg[n] = 0;
    g_cnt[n] = 0;
}

// ---------------------------------------------------------------------------
// Kernel B: edge_sum[e] = sum_m (H[m]*w2[m]); node-degree histogram.
// Product rounded separately from add.
// ---------------------------------------------------------------------------
__global__ __launch_bounds__(128) void kB(const int* __restrict__ mn,
                                          const float* __restrict__ H)
{
    int e = blockIdx.x;
    __shared__ int   mem[EDGESZ];
    __shared__ float w2e[EDGESZ];
    int t = threadIdx.x;
    if (t < EDGESZ) {
        int node = mn[e * EDGESZ + t];
        mem[t] = node;
        w2e[t] = g_w2[node];
        atomicAdd(&g_deg[node], 1);
    }
    __syncthreads();
    float s = 0.f;
#pragma unroll
    for (int i = 0; i < EDGESZ; i++)
        s = __fadd_rn(s, __fmul_rn(H[(size_t)mem[i] * DIM + t], w2e[i]));
    g_edge_sum[(size_t)e * DIM + t] = s;
}

// ---------------------------------------------------------------------------
// Kernel Off: per-node segment offsets via warp-aggregated atomic counter
// ---------------------------------------------------------------------------
__global__ __launch_bounds__(256) void kOff()
{
    int n = blockIdx.x * 256 + threadIdx.x;
    int lane = threadIdx.x & 31;
    int deg = (n < NNODES) ? g_deg[n] : 0;
    int x = deg;
#pragma unroll
    for (int o = 1; o < 32; o <<= 1) {
        int y = __shfl_up_sync(0xffffffffu, x, o);
        if (lane >= o) x += y;
    }
    int total = __shfl_sync(0xffffffffu, x, 31);
    int base = 0;
    if (lane == 0) base = atomicAdd(&g_ctr, total);
    base = __shfl_sync(0xffffffffu, base, 0);
    if (n < NNODES) g_off[n] = base + x - deg;
}

// ---------------------------------------------------------------------------
// Scatter: build node -> incident-edge list (edge id == membership >> 4)
// ---------------------------------------------------------------------------
__global__ __launch_bounds__(256) void kScat(const int* __restrict__ mn)
{
    int m = blockIdx.x * 256 + threadIdx.x;
    if (m >= NMEMB) return;
    int node = mn[m];
    int pos = g_off[node] + atomicAdd(&g_cnt[node], 1);
    g_elist[pos] = m >> 4;
}

// ---------------------------------------------------------------------------
// Sort each node's edge segment ascending -> deterministic gather order
// (also matches reference segment_sum's ascending-membership accumulation).
// One thread per node; insertion sort (avg deg ~8, elist is L2-resident).
// ---------------------------------------------------------------------------
__global__ __launch_bounds__(256) void kSort()
{
    int n = blockIdx.x * 256 + threadIdx.x;
    if (n >= NNODES) return;
    int st = g_off[n];
    int deg = g_deg[n];
    for (int i = 1; i < deg; i++) {
        int key = g_elist[st + i];
        int j = i - 1;
        while (j >= 0 && g_elist[st + j] > key) {
            g_elist[st + j + 1] = g_elist[st + j];
            j--;
        }
        g_elist[st + j + 1] = key;
    }
}

// ---------------------------------------------------------------------------
// Fused: gather edge sums -> new_signal (smem) -> double-precision rowsum
//        -> scale -> GEMM + bias.
// Block = 128 threads handles 32 nodes; thread owns output column t.
// ---------------------------------------------------------------------------
__global__ __launch_bounds__(128) void kFE(const float* __restrict__ H,
                                           const float* __restrict__ W,
                                           const float* __restrict__ bias,
                                           float* __restrict__ out)
{
    __shared__ float  sA[32 * DIM];
    __shared__ double sRed[32 * 4];
    __shared__ float  sRinv[32];
    int t = threadIdx.x;
    int w = t >> 5, lane = t & 31;
    int base = blockIdx.x * 32;
    const float inv15 = 1.f / 15.f;

    // Phase 1: build new_signal rows; per-row warp partial sums (double)
#pragma unroll 1
    for (int i = 0; i < 32; i++) {
        int n = base + i;
        int deg = g_deg[n];
        int st  = g_off[n];
        float s = 0.f;
        int j = 0;
        for (; j + 4 <= deg; j += 4) {
            float v0 = g_edge_sum[(size_t)g_elist[st + j + 0] * DIM + t];
            float v1 = g_edge_sum[(size_t)g_elist[st + j + 1] * DIM + t];
            float v2 = g_edge_sum[(size_t)g_elist[st + j + 2] * DIM + t];
            float v3 = g_edge_sum[(size_t)g_elist[st + j + 3] * DIM + t];
            s = __fadd_rn(__fadd_rn(__fadd_rn(__fadd_rn(s, v0), v1), v2), v3);
        }
        for (; j < deg; j++)
            s = __fadd_rn(s, g_edge_sum[(size_t)g_elist[st + j] * DIM + t]);
        float nv = fmaf(H[(size_t)n * DIM + t], 1.f - (float)deg * inv15,
                        s * inv15);
        sA[i * DIM + t] = nv;
        // double-precision 32-lane shfl tree
        double v = (double)nv;
#pragma unroll
        for (int o = 16; o > 0; o >>= 1)
            v += __shfl_xor_sync(0xffffffffu, v, o);
        if (lane == 0) sRed[i * 4 + w] = v;
    }
    __syncthreads();

    // Phase 2: rowsum (double) -> rinv (float)
    if (t < 32) {
        double rowsum = ((sRed[t * 4 + 0] + sRed[t * 4 + 1])
                          + sRed[t * 4 + 2]) + sRed[t * 4 + 3];
        sRinv[t] = (rowsum != 0.0) ? (float)(1.0 / rowsum) : 0.f;
    }
    __syncthreads();

    // Phase 2b: scale rows in smem
#pragma unroll
    for (int i = 0; i < 32; i++)
        sA[i * DIM + t] = __fmul_rn(sA[i * DIM + t], sRinv[i]);
    __syncthreads();

    // Phase 3: GEMM with packed f32x2 FFMA
    unsigned long long acc[32];
#pragma unroll
    for (int i = 0; i < 32; i++) acc[i] = 0ull;

#pragma unroll 1
    for (int k = 0; k < DIM; k += 8) {
        unsigned long long wp0 = pk2(W[(k + 0) * DIM + t], W[(k + 1) * DIM + t]);
        unsigned long long wp1 = pk2(W[(k + 2) * DIM + t], W[(k + 3) * DIM + t]);
        unsigned long long wp2 = pk2(W[(k + 4) * DIM + t], W[(k + 5) * DIM + t]);
        unsigned long long wp3 = pk2(W[(k + 6) * DIM + t], W[(k + 7) * DIM + t]);
        const float4* arow = reinterpret_cast<const float4*>(sA + k);
#pragma unroll
        for (int i = 0; i < 32; i++) {
            float4 a0 = arow[i * (DIM / 4) + 0];
            float4 a1 = arow[i * (DIM / 4) + 1];
            fma2(acc[i], pk2(a0.x, a0.y), wp0);
            fma2(acc[i], pk2(a0.z, a0.w), wp1);
            fma2(acc[i], pk2(a1.x, a1.y), wp2);
            fma2(acc[i], pk2(a1.z, a1.w), wp3);
        }
    }
    float b = bias[t];
    size_t obase = (size_t)base * DIM;
#pragma unroll
    for (int i = 0; i < 32; i++) {
        float lo, hi;
        unpk2(lo, hi, acc[i]);
        out[obase + (size_t)i * DIM + t] = lo + hi + b;
    }
}

// ---------------------------------------------------------------------------
extern "C" void kernel_launch(void* const* d_in, const int* in_sizes, int n_in,
                              void* d_out, int out_size)
{
    const int*   member_nodes = (const int*)  d_in[0];
    const float* H            = (const float*)d_in[2];
    const float* input_weight = (const float*)d_in[3];
    const float* W            = (const float*)d_in[4];
    const float* bias         = (const float*)d_in[5];
    const float* fc1_w        = (const float*)d_in[6];
    const float* fc1_b        = (const float*)d_in[7];
    const float* fc2_w        = (const float*)d_in[8];
    const float* fc2_b        = (const float*)d_in[9];
    const float* fc3_w        = (const float*)d_in[10];
    const float* fc3_b        = (const float*)d_in[11];
    float* out = (float*)d_out;

    kW<<<(NNODES + 255) / 256, 256>>>(input_weight,
                                      fc1_w, fc1_b, fc2_w, fc2_b, fc3_w, fc3_b);
    kB<<<NEDGES, 128>>>(member_nodes, H);
    kOff<<<(NNODES + 255) / 256, 256>>>();
    kScat<<<(NMEMB + 255) / 256, 256>>>(member_nodes);
    kSort<<<(NNODES + 255) / 256, 256>>>();
    kFE<<<NNODES / 32, 128>>>(H, W, bias, out);
}

// round 6
// speedup vs baseline: 1.0031x; 1.0031x over previous
#include <cuda_runtime.h>
#include <cuda_bf16.h>
#include <cstdint>

// Problem constants (fixed by the dataset's setup_inputs)
#define NNODES 100000
#define NEDGES 50000
#define EDGESZ 16
#define NMEMB  (NEDGES * EDGESZ)   // 800000
#define DIM    128

// Scratch (allocation-free rule: __device__ globals)
__device__ float g_w2[NNODES];
__device__ float g_edge_sum[(size_t)NEDGES * DIM];
__device__ int   g_deg[NNODES];
__device__ int   g_cnt[NNODES];
__device__ int   g_off[NNODES];
__device__ int   g_elist[NMEMB];   // node -> list of incident edges
__device__ int   g_ctr;

// ---------------------------------------------------------------------------
// packed f32x2 helpers
// ---------------------------------------------------------------------------
__device__ __forceinline__ void fma2(unsigned long long& d,
                                     unsigned long long a, unsigned long long b)
{
    asm("fma.rn.f32x2 %0, %1, %2, %0;" : "+l"(d) : "l"(a), "l"(b));
}
__device__ __forceinline__ unsigned long long pk2(float lo, float hi)
{
    unsigned long long r;
    asm("mov.b64 %0, {%1, %2};" : "=l"(r) : "f"(lo), "f"(hi));
    return r;
}
__device__ __forceinline__ void unpk2(float& lo, float& hi, unsigned long long v)
{
    asm("mov.b64 {%0, %1}, %2;" : "=f"(lo), "=f"(hi) : "l"(v));
}

// ---------------------------------------------------------------------------
// Kernel W: per-node MLP -> w2[n]; zero deg/cnt/ctr
// ---------------------------------------------------------------------------
__global__ __launch_bounds__(256) void kW(
    const float* __restrict__ iw,
    const float* __restrict__ fc1w, const float* __restrict__ fc1b,
    const float* __restrict__ fc2w, const float* __restrict__ fc2b,
    const float* __restrict__ fc3w, const float* __restrict__ fc3b)
{
    int n = blockIdx.x * 256 + threadIdx.x;
    if (n == 0) g_ctr = 0;
    if (n >= NNODES) return;
    float x0 = iw[n * 2 + 0];
    float x1 = iw[n * 2 + 1];
    float h1[10];
#pragma unroll
    for (int j = 0; j < 10; j++)
        h1[j] = fmaxf(0.f, fmaf(x0, fc1w[j], fmaf(x1, fc1w[10 + j], fc1b[j])));
    float h2[5];
#pragma unroll
    for (int j = 0; j < 5; j++) {
        float s = fc2b[j];
#pragma unroll
        for (int k = 0; k < 10; k++) s = fmaf(h1[k], fc2w[k * 5 + j], s);
        h2[j] = fmaxf(0.f, s);
    }
    float z = fc3b[0];
#pragma unroll
    for (int k = 0; k < 5; k++) z = fmaf(h2[k], fc3w[k], z);
    g_w2[n] = 1.f / (1.f + expf(-z));
    g_deg[n] = 0;
    g_cnt[n] = 0;
}

// ---------------------------------------------------------------------------
// Kernel B: edge_sum[e] = sum_m (H[m]*w2[m]); node-degree histogram.
// Product rounded separately from add.
// ---------------------------------------------------------------------------
__global__ __launch_bounds__(128) void kB(const int* __restrict__ mn,
                                          const float* __restrict__ H)
{
    int e = blockIdx.x;
    __shared__ int   mem[EDGESZ];
    __shared__ float w2e[EDGESZ];
    int t = threadIdx.x;
    if (t < EDGESZ) {
        int node = mn[e * EDGESZ + t];
        mem[t] = node;
        w2e[t] = g_w2[node];
        atomicAdd(&g_deg[node], 1);
    }
    __syncthreads();
    float s = 0.f;
#pragma unroll
    for (int i = 0; i < EDGESZ; i++)
        s = __fadd_rn(s, __fmul_rn(H[(size_t)mem[i] * DIM + t], w2e[i]));
    g_edge_sum[(size_t)e * DIM + t] = s;
}

// ---------------------------------------------------------------------------
// Kernel Off: per-node segment offsets via warp-aggregated atomic counter
// ---------------------------------------------------------------------------
__global__ __launch_bounds__(256) void kOff()
{
    int n = blockIdx.x * 256 + threadIdx.x;
    int lane = threadIdx.x & 31;
    int deg = (n < NNODES) ? g_deg[n] : 0;
    int x = deg;
#pragma unroll
    for (int o = 1; o < 32; o <<= 1) {
        int y = __shfl_up_sync(0xffffffffu, x, o);
        if (lane >= o) x += y;
    }
    int total = __shfl_sync(0xffffffffu, x, 31);
    int base = 0;
    if (lane == 0) base = atomicAdd(&g_ctr, total);
    base = __shfl_sync(0xffffffffu, base, 0);
    if (n < NNODES) g_off[n] = base + x - deg;
}

// ---------------------------------------------------------------------------
// Scatter: build node -> incident-edge list (edge id == membership >> 4)
// ---------------------------------------------------------------------------
__global__ __launch_bounds__(256) void kScat(const int* __restrict__ mn)
{
    int m = blockIdx.x * 256 + threadIdx.x;
    if (m >= NMEMB) return;
    int node = mn[m];
    int pos = g_off[node] + atomicAdd(&g_cnt[node], 1);
    g_elist[pos] = m >> 4;
}

// ---------------------------------------------------------------------------
// Sort each node's edge segment ascending -> deterministic gather order
// (also matches reference segment_sum's ascending-membership accumulation).
// One thread per node; insertion sort (avg deg ~8, elist is L2-resident).
// ---------------------------------------------------------------------------
__global__ __launch_bounds__(256) void kSort()
{
    int n = blockIdx.x * 256 + threadIdx.x;
    if (n >= NNODES) return;
    int st = g_off[n];
    int deg = g_deg[n];
    for (int i = 1; i < deg; i++) {
        int key = g_elist[st + i];
        int j = i - 1;
        while (j >= 0 && g_elist[st + j] > key) {
            g_elist[st + j + 1] = g_elist[st + j];
            j--;
        }
        g_elist[st + j + 1] = key;
    }
}

// ---------------------------------------------------------------------------
// Fused: gather edge sums -> new_signal (smem) -> double-precision rowsum
//        -> scale -> GEMM + bias.
// Block = 128 threads handles 32 nodes; thread owns output column t.
// ---------------------------------------------------------------------------
__global__ __launch_bounds__(128) void kFE(const float* __restrict__ H,
                                           const float* __restrict__ W,
                                           const float* __restrict__ bias,
                                           float* __restrict__ out)
{
    __shared__ float  sA[32 * DIM];
    __shared__ double sRed[32 * 4];
    __shared__ float  sRinv[32];
    int t = threadIdx.x;
    int w = t >> 5, lane = t & 31;
    int base = blockIdx.x * 32;
    const float inv15 = 1.f / 15.f;

    // Phase 1: build new_signal rows; per-row warp partial sums (double)
#pragma unroll 1
    for (int i = 0; i < 32; i++) {
        int n = base + i;
        int deg = g_deg[n];
        int st  = g_off[n];
        float s = 0.f;
        int j = 0;
        for (; j + 4 <= deg; j += 4) {
            float v0 = g_edge_sum[(size_t)g_elist[st + j + 0] * DIM + t];
            float v1 = g_edge_sum[(size_t)g_elist[st + j + 1] * DIM + t];
            float v2 = g_edge_sum[(size_t)g_elist[st + j + 2] * DIM + t];
            float v3 = g_edge_sum[(size_t)g_elist[st + j + 3] * DIM + t];
            s = __fadd_rn(__fadd_rn(__fadd_rn(__fadd_rn(s, v0), v1), v2), v3);
        }
        for (; j < deg; j++)
            s = __fadd_rn(s, g_edge_sum[(size_t)g_elist[st + j] * DIM + t]);
        float nv = fmaf(H[(size_t)n * DIM + t], 1.f - (float)deg * inv15,
                        s * inv15);
        sA[i * DIM + t] = nv;
        // double-precision 32-lane shfl tree
        double v = (double)nv;
#pragma unroll
        for (int o = 16; o > 0; o >>= 1)
            v += __shfl_xor_sync(0xffffffffu, v, o);
        if (lane == 0) sRed[i * 4 + w] = v;
    }
    __syncthreads();

    // Phase 2: rowsum (double) -> rinv (float)
    if (t < 32) {
        double rowsum = ((sRed[t * 4 + 0] + sRed[t * 4 + 1])
                          + sRed[t * 4 + 2]) + sRed[t * 4 + 3];
        sRinv[t] = (rowsum != 0.0) ? (float)(1.0 / rowsum) : 0.f;
    }
    __syncthreads();

    // Phase 2b: scale rows in smem
#pragma unroll
    for (int i = 0; i < 32; i++)
        sA[i * DIM + t] = __fmul_rn(sA[i * DIM + t], sRinv[i]);
    __syncthreads();

    // Phase 3: GEMM with packed f32x2 FFMA
    unsigned long long acc[32];
#pragma unroll
    for (int i = 0; i < 32; i++) acc[i] = 0ull;

#pragma unroll 1
    for (int k = 0; k < DIM; k += 8) {
        unsigned long long wp0 = pk2(W[(k + 0) * DIM + t], W[(k + 1) * DIM + t]);
        unsigned long long wp1 = pk2(W[(k + 2) * DIM + t], W[(k + 3) * DIM + t]);
        unsigned long long wp2 = pk2(W[(k + 4) * DIM + t], W[(k + 5) * DIM + t]);
        unsigned long long wp3 = pk2(W[(k + 6) * DIM + t], W[(k + 7) * DIM + t]);
        const float4* arow = reinterpret_cast<const float4*>(sA + k);
#pragma unroll
        for (int i = 0; i < 32; i++) {
            float4 a0 = arow[i * (DIM / 4) + 0];
            float4 a1 = arow[i * (DIM / 4) + 1];
            fma2(acc[i], pk2(a0.x, a0.y), wp0);
            fma2(acc[i], pk2(a0.z, a0.w), wp1);
            fma2(acc[i], pk2(a1.x, a1.y), wp2);
            fma2(acc[i], pk2(a1.z, a1.w), wp3);
        }
    }
    float b = bias[t];
    size_t obase = (size_t)base * DIM;
#pragma unroll
    for (int i = 0; i < 32; i++) {
        float lo, hi;
        unpk2(lo, hi, acc[i]);
        out[obase + (size_t)i * DIM + t] = lo + hi + b;
    }
}

// ---------------------------------------------------------------------------
extern "C" void kernel_launch(void* const* d_in, const int* in_sizes, int n_in,
                              void* d_out, int out_size)
{
    const int*   member_nodes = (const int*)  d_in[0];
    const float* H            = (const float*)d_in[2];
    const float* input_weight = (const float*)d_in[3];
    const float* W            = (const float*)d_in[4];
    const float* bias         = (const float*)d_in[5];
    const float* fc1_w        = (const float*)d_in[6];
    const float* fc1_b        = (const float*)d_in[7];
    const float* fc2_w        = (const float*)d_in[8];
    const float* fc2_b        = (const float*)d_in[9];
    const float* fc3_w        = (const float*)d_in[10];
    const float* fc3_b        = (const float*)d_in[11];
    float* out = (float*)d_out;

    kW<<<(NNODES + 255) / 256, 256>>>(input_weight,
                                      fc1_w, fc1_b, fc2_w, fc2_b, fc3_w, fc3_b);
    kB<<<NEDGES, 128>>>(member_nodes, H);
    kOff<<<(NNODES + 255) / 256, 256>>>();
    kScat<<<(NMEMB + 255) / 256, 256>>>(member_nodes);
    kSort<<<(NNODES + 255) / 256, 256>>>();
    kFE<<<NNODES / 32, 128>>>(H, W, bias, out);
}

// round 7
// speedup vs baseline: 1.3773x; 1.3731x over previous
#include <cuda_runtime.h>
#include <cuda_bf16.h>
#include <cstdint>

// Problem constants (fixed by the dataset's setup_inputs)
#define NNODES 100000
#define NEDGES 50000
#define EDGESZ 16
#define NMEMB  (NEDGES * EDGESZ)   // 800000
#define DIM    128

// Scratch (allocation-free rule: __device__ globals)
__device__ float g_w2[NNODES];
__device__ float g_edge_sum[(size_t)NEDGES * DIM];
__device__ int   g_deg[NNODES];
__device__ int   g_cnt[NNODES];
__device__ int   g_off[NNODES];
__device__ int   g_elist[NMEMB];   // node -> list of incident edges
__device__ int   g_ctr;

// ---------------------------------------------------------------------------
// packed f32x2 helpers
// ---------------------------------------------------------------------------
__device__ __forceinline__ void fma2(unsigned long long& d,
                                     unsigned long long a, unsigned long long b)
{
    asm("fma.rn.f32x2 %0, %1, %2, %0;" : "+l"(d) : "l"(a), "l"(b));
}
__device__ __forceinline__ unsigned long long pk2(float lo, float hi)
{
    unsigned long long r;
    asm("mov.b64 %0, {%1, %2};" : "=l"(r) : "f"(lo), "f"(hi));
    return r;
}
__device__ __forceinline__ void unpk2(float& lo, float& hi, unsigned long long v)
{
    asm("mov.b64 {%0, %1}, %2;" : "=f"(lo), "=f"(hi) : "l"(v));
}

// ---------------------------------------------------------------------------
// Kernel W: per-node MLP -> w2[n]; zero deg/cnt/ctr
// ---------------------------------------------------------------------------
__global__ __launch_bounds__(256) void kW(
    const float* __restrict__ iw,
    const float* __restrict__ fc1w, const float* __restrict__ fc1b,
    const float* __restrict__ fc2w, const float* __restrict__ fc2b,
    const float* __restrict__ fc3w, const float* __restrict__ fc3b)
{
    int n = blockIdx.x * 256 + threadIdx.x;
    if (n == 0) g_ctr = 0;
    if (n >= NNODES) return;
    float x0 = iw[n * 2 + 0];
    float x1 = iw[n * 2 + 1];
    float h1[10];
#pragma unroll
    for (int j = 0; j < 10; j++)
        h1[j] = fmaxf(0.f, fmaf(x0, fc1w[j], fmaf(x1, fc1w[10 + j], fc1b[j])));
    float h2[5];
#pragma unroll
    for (int j = 0; j < 5; j++) {
        float s = fc2b[j];
#pragma unroll
        for (int k = 0; k < 10; k++) s = fmaf(h1[k], fc2w[k * 5 + j], s);
        h2[j] = fmaxf(0.f, s);
    }
    float z = fc3b[0];
#pragma unroll
    for (int k = 0; k < 5; k++) z = fmaf(h2[k], fc3w[k], z);
    g_w2[n] = 1.f / (1.f + expf(-z));
    g_deg[n] = 0;
    g_cnt[n] = 0;
}

// ---------------------------------------------------------------------------
// Kernel B: edge_sum[e] = sum_m (H[m]*w2[m]); node-degree histogram.
// ---------------------------------------------------------------------------
__global__ __launch_bounds__(128) void kB(const int* __restrict__ mn,
                                          const float* __restrict__ H)
{
    int e = blockIdx.x;
    __shared__ int   mem[EDGESZ];
    __shared__ float w2e[EDGESZ];
    int t = threadIdx.x;
    if (t < EDGESZ) {
        int node = mn[e * EDGESZ + t];
        mem[t] = node;
        w2e[t] = g_w2[node];
        atomicAdd(&g_deg[node], 1);
    }
    __syncthreads();
    float s = 0.f;
#pragma unroll
    for (int i = 0; i < EDGESZ; i++)
        s = __fadd_rn(s, __fmul_rn(H[(size_t)mem[i] * DIM + t], w2e[i]));
    g_edge_sum[(size_t)e * DIM + t] = s;
}

// ---------------------------------------------------------------------------
// Kernel Off: per-node segment offsets via warp-aggregated atomic counter
// ---------------------------------------------------------------------------
__global__ __launch_bounds__(256) void kOff()
{
    int n = blockIdx.x * 256 + threadIdx.x;
    int lane = threadIdx.x & 31;
    int deg = (n < NNODES) ? g_deg[n] : 0;
    int x = deg;
#pragma unroll
    for (int o = 1; o < 32; o <<= 1) {
        int y = __shfl_up_sync(0xffffffffu, x, o);
        if (lane >= o) x += y;
    }
    int total = __shfl_sync(0xffffffffu, x, 31);
    int base = 0;
    if (lane == 0) base = atomicAdd(&g_ctr, total);
    base = __shfl_sync(0xffffffffu, base, 0);
    if (n < NNODES) g_off[n] = base + x - deg;
}

// ---------------------------------------------------------------------------
// Scatter: build node -> incident-edge list (edge id == membership >> 4)
// ---------------------------------------------------------------------------
__global__ __launch_bounds__(256) void kScat(const int* __restrict__ mn)
{
    int m = blockIdx.x * 256 + threadIdx.x;
    if (m >= NMEMB) return;
    int node = mn[m];
    int pos = g_off[node] + atomicAdd(&g_cnt[node], 1);
    g_elist[pos] = m >> 4;
}

// ---------------------------------------------------------------------------
// Sort each node's edge segment ascending -> deterministic gather order
// matching the reference's ascending-membership accumulation.
// ---------------------------------------------------------------------------
__global__ __launch_bounds__(256) void kSort()
{
    int n = blockIdx.x * 256 + threadIdx.x;
    if (n >= NNODES) return;
    int st = g_off[n];
    int deg = g_deg[n];
    for (int i = 1; i < deg; i++) {
        int key = g_elist[st + i];
        int j = i - 1;
        while (j >= 0 && g_elist[st + j] > key) {
            g_elist[st + j + 1] = g_elist[st + j];
            j--;
        }
        g_elist[st + j + 1] = key;
    }
}

// ---------------------------------------------------------------------------
// Fused: gather -> new_signal (smem) -> parallel double rowsum -> scale ->
// GEMM + bias.  256 threads: half h = t>>7 handles 16 rows, col = t&127.
// ---------------------------------------------------------------------------
__global__ __launch_bounds__(256) void kFE(const float* __restrict__ H,
                                           const float* __restrict__ W,
                                           const float* __restrict__ bias,
                                           float* __restrict__ out)
{
    __shared__ float sA[32 * DIM];
    __shared__ float sRinv[32];
    int t = threadIdx.x;
    int h = t >> 7;          // half-block id (0/1)
    int col = t & 127;       // output / feature column
    int base = blockIdx.x * 32;
    const float inv15 = 1.f / 15.f;

    // Phase 1: build new_signal rows (16 per half); same per-row numerics as R6
#pragma unroll 1
    for (int i = 0; i < 16; i++) {
        int r = h * 16 + i;
        int n = base + r;
        int deg = g_deg[n];
        int st  = g_off[n];
        float s = 0.f;
        int j = 0;
        for (; j + 4 <= deg; j += 4) {
            float v0 = g_edge_sum[(size_t)g_elist[st + j + 0] * DIM + col];
            float v1 = g_edge_sum[(size_t)g_elist[st + j + 1] * DIM + col];
            float v2 = g_edge_sum[(size_t)g_elist[st + j + 2] * DIM + col];
            float v3 = g_edge_sum[(size_t)g_elist[st + j + 3] * DIM + col];
            s = __fadd_rn(__fadd_rn(__fadd_rn(__fadd_rn(s, v0), v1), v2), v3);
        }
        for (; j < deg; j++)
            s = __fadd_rn(s, g_edge_sum[(size_t)g_elist[st + j] * DIM + col]);
        sA[r * DIM + col] = fmaf(H[(size_t)n * DIM + col],
                                 1.f - (float)deg * inv15, s * inv15);
    }
    __syncthreads();

    // Phase 2: double-precision rowsum, fully parallel: 8 threads per row
    {
        int r = t >> 3;          // row 0..31
        int c = t & 7;           // chunk within row
        const float4* p = reinterpret_cast<const float4*>(sA + r * DIM + c * 16);
        double v = 0.0;
#pragma unroll
        for (int q = 0; q < 4; q++) {
            float4 a = p[q];
            v += ((double)a.x + (double)a.y) + ((double)a.z + (double)a.w);
        }
#pragma unroll
        for (int o = 1; o < 8; o <<= 1)
            v += __shfl_xor_sync(0xffffffffu, v, o);
        if (c == 0)
            sRinv[r] = (v != 0.0) ? (float)(1.0 / v) : 0.f;
    }
    __syncthreads();

    // Phase 2b: scale own half's rows
#pragma unroll
    for (int i = 0; i < 16; i++) {
        int r = h * 16 + i;
        sA[r * DIM + col] = __fmul_rn(sA[r * DIM + col], sRinv[r]);
    }
    __syncthreads();

    // Phase 3: GEMM for own half's 16 rows; A loaded as register pairs
    unsigned long long acc[16];
#pragma unroll
    for (int i = 0; i < 16; i++) acc[i] = 0ull;

#pragma unroll 1
    for (int k = 0; k < DIM; k += 8) {
        unsigned long long wp0 = pk2(W[(k + 0) * DIM + col], W[(k + 1) * DIM + col]);
        unsigned long long wp1 = pk2(W[(k + 2) * DIM + col], W[(k + 3) * DIM + col]);
        unsigned long long wp2 = pk2(W[(k + 4) * DIM + col], W[(k + 5) * DIM + col]);
        unsigned long long wp3 = pk2(W[(k + 6) * DIM + col], W[(k + 7) * DIM + col]);
        const ulonglong2* arow =
            reinterpret_cast<const ulonglong2*>(sA + (h * 16) * DIM + k);
#pragma unroll
        for (int i = 0; i < 16; i++) {
            ulonglong2 a0 = arow[i * (DIM / 4)];       // floats k .. k+3
            ulonglong2 a1 = arow[i * (DIM / 4) + 1];   // floats k+4 .. k+7
            fma2(acc[i], a0.x, wp0);
            fma2(acc[i], a0.y, wp1);
            fma2(acc[i], a1.x, wp2);
            fma2(acc[i], a1.y, wp3);
        }
    }
    float b = bias[col];
    size_t obase = (size_t)(base + h * 16) * DIM;
#pragma unroll
    for (int i = 0; i < 16; i++) {
        float lo, hi;
        unpk2(lo, hi, acc[i]);
        out[obase + (size_t)i * DIM + col] = lo + hi + b;
    }
}

// ---------------------------------------------------------------------------
extern "C" void kernel_launch(void* const* d_in, const int* in_sizes, int n_in,
                              void* d_out, int out_size)
{
    const int*   member_nodes = (const int*)  d_in[0];
    const float* H            = (const float*)d_in[2];
    const float* input_weight = (const float*)d_in[3];
    const float* W            = (const float*)d_in[4];
    const float* bias         = (const float*)d_in[5];
    const float* fc1_w        = (const float*)d_in[6];
    const float* fc1_b        = (const float*)d_in[7];
    const float* fc2_w        = (const float*)d_in[8];
    const float* fc2_b        = (const float*)d_in[9];
    const float* fc3_w        = (const float*)d_in[10];
    const float* fc3_b        = (const float*)d_in[11];
    float* out = (float*)d_out;

    kW<<<(NNODES + 255) / 256, 256>>>(input_weight,
                                      fc1_w, fc1_b, fc2_w, fc2_b, fc3_w, fc3_b);
    kB<<<NEDGES, 128>>>(member_nodes, H);
    kOff<<<(NNODES + 255) / 256, 256>>>();
    kScat<<<(NMEMB + 255) / 256, 256>>>(member_nodes);
    kSort<<<(NNODES + 255) / 256, 256>>>();
    kFE<<<NNODES / 32, 256>>>(H, W, bias, out);
}